// round 15
// baseline (speedup 1.0000x reference)
#include <cuda_runtime.h>

// DepthLoss3D, two PDL-overlapped kernels.
// Node 1 (48 blocks): sorts each (channel,group) once (static bitonic, R6),
//   scans, publishes g_sorted/g_prefix, stores per-group diagonal partials,
//   zeroes out[0..2]. Triggers programmatic completion at START so node 2's
//   prologue fully overlaps (gridsync still waits for full completion).
// Node 2 (363 blocks, PDL): 360 pair blocks decode + load p (independent of
//   node 1), gridsync, copy sorted+prefix to shared, 3 binary searches ->
//   proven closed form; 3 finisher blocks sum the 16 diag partials per channel.
//   f(x)=max(x-ds,0.2ds-x,0)-0.2ds*[x<0], x=p-pb, ds>0:
//   sum = n1*k1 - P[n1] + (T-P[n2]) - (256-n2)*k2 - 0.2ds*(256-n3)

#define N_ELEM 4096

__device__ float g_sorted[3][16][256];
__device__ float g_prefix[3][16][257];
__device__ float g_diag[48];

__device__ __forceinline__ int elem_index(int c, int g, int m) {
    if (c == 0)      return (g << 8) + m;
    else if (c == 1) return ((m >> 4) << 8) + (g << 4) + (m & 15);
    else             return (m << 4) + g;
}

__global__ void __launch_bounds__(256) sort_kernel(
    const float* __restrict__ pred,
    float* __restrict__ out)
{
    // Let the dependent kernel launch immediately; its gridsync still waits
    // for this kernel's completion + memory visibility.
    cudaTriggerProgrammaticLaunchCompletion();

    __shared__ float sv[256];
    __shared__ float red[8];

    const int t    = threadIdx.x;
    const int lane = t & 31;
    const int wid  = t >> 5;
    const int c    = blockIdx.x >> 4;
    const int g    = blockIdx.x & 15;

    if (blockIdx.x == 0 && t < 3) out[t] = 0.0f;  // node2 atomics are post-gridsync

    float v = pred[elem_index(c, g, t) * 3 + c];

    // ---- Static bitonic sort network (ascending by rank t), proven R6. ----
    const bool u2   = !(t & 2);
    const bool u4   = !(t & 4);
    const bool u8   = !(t & 8);
    const bool u16  = !(t & 16);
    const bool u32  = !(t & 32);
    const bool u64  = !(t & 64);
    const bool u128 = !(t & 128);

#define SH(J, UP) do {                                              \
        const float o_ = __shfl_xor_sync(0xffffffffu, v, (J));      \
        const bool mn_ = (((t & (J)) == 0) == (UP));                \
        v = mn_ ? fminf(v, o_) : fmaxf(v, o_);                      \
    } while (0)

#define SM(J, UP) do {                                              \
        sv[t] = v;                                                  \
        __syncthreads();                                            \
        const float o_ = sv[t ^ (J)];                               \
        const bool mn_ = (((t & (J)) == 0) == (UP));                \
        v = mn_ ? fminf(v, o_) : fmaxf(v, o_);                      \
        __syncthreads();                                            \
    } while (0)

    SH(1, u2);
    SH(2, u4);  SH(1, u4);
    SH(4, u8);  SH(2, u8);  SH(1, u8);
    SH(8, u16); SH(4, u16); SH(2, u16); SH(1, u16);
    SH(16, u32); SH(8, u32); SH(4, u32); SH(2, u32); SH(1, u32);
    SM(32, u64); SH(16, u64); SH(8, u64); SH(4, u64); SH(2, u64); SH(1, u64);
    SM(64, u128); SM(32, u128); SH(16, u128); SH(8, u128); SH(4, u128);
    SH(2, u128); SH(1, u128);
    SM(128, true); SM(64, true); SM(32, true); SH(16, true); SH(8, true);
    SH(4, true); SH(2, true); SH(1, true);

#undef SH
#undef SM

    // ---- Inclusive prefix scan of sorted v. ----
    float x = v;
#pragma unroll
    for (int off = 1; off < 32; off <<= 1) {
        const float y = __shfl_up_sync(0xffffffffu, x, off);
        if (lane >= off) x += y;
    }
    if (lane == 31) red[wid] = x;
    __syncthreads();
    float woff = 0.0f;
#pragma unroll
    for (int w = 0; w < 8; ++w)
        woff += (w < wid) ? red[w] : 0.0f;

    g_sorted[c][g][t]     = v;
    g_prefix[c][g][t + 1] = x + woff;
    if (t == 0) g_prefix[c][g][0] = 0.0f;

    // ---- Diagonal partial for this group: sum_r v_(r)*(2r-255). ----
    float w = v * (float)(2 * t - 255);
#pragma unroll
    for (int off = 16; off > 0; off >>= 1)
        w += __shfl_xor_sync(0xffffffffu, w, off);
    __syncthreads();
    if (lane == 0) red[wid] = w;
    __syncthreads();
    if (t == 0)
        g_diag[blockIdx.x] = red[0] + red[1] + red[2] + red[3]
                           + red[4] + red[5] + red[6] + red[7];
}

__global__ void __launch_bounds__(256) query_kernel(
    const float* __restrict__ pred,
    const float* __restrict__ spac,
    float* __restrict__ out)
{
    __shared__ float sv[256];
    __shared__ float sp[257];
    __shared__ float red[8];

    const int t    = threadIdx.x;
    const int lane = t & 31;
    const int wid  = t >> 5;
    const int bx   = blockIdx.x;

    const float inv = 1.0f / ((float)N_ELEM * (float)N_ELEM);

    if (bx >= 360) {
        // Finisher: sum 16 diagonal partials for channel c.
        const int c = bx - 360;
        cudaGridDependencySynchronize();
        float w = (lane < 16 && wid == 0) ? g_diag[c * 16 + lane] : 0.0f;
        if (wid == 0) {
#pragma unroll
            for (int off = 8; off > 0; off >>= 1)
                w += __shfl_xor_sync(0xffffffffu, w, off);
            if (lane == 0) atomicAdd(&out[c], w * inv);
        }
        return;
    }

    // ---- Pair prologue (independent of node 1). ----
    const int c  = bx / 120;
    const int pq = bx - c * 120;
    int a = 1;
    while ((a + 1) * a / 2 <= pq) ++a;
    const int b = pq - a * (a - 1) / 2;

    const float p  = pred[elem_index(c, a, t) * 3 + c];
    const float k  = spac[c] * 2.0f;
    const float ds = (float)a * k - (float)b * k;   // reference rounding order
    const float c1 = 0.2f * ds;
    const float k1 = p - ds;
    const float k2 = p - c1;

    // ---- Wait for node 1 results, stage them in shared. ----
    cudaGridDependencySynchronize();
    sv[t] = g_sorted[c][b][t];
    sp[t] = g_prefix[c][b][t];
    if (t == 0) sp[256] = g_prefix[c][b][256];
    __syncthreads();

    // ---- Closed form (proven). ----
    int cnt1 = 0, cnt2 = 0, cnt3 = 0;
#pragma unroll
    for (int s = 128; s > 0; s >>= 1) {
        cnt1 += (sv[cnt1 + s - 1] <  k1) ? s : 0;
        cnt2 += (sv[cnt2 + s - 1] <= k2) ? s : 0;
        cnt3 += (sv[cnt3 + s - 1] <= p ) ? s : 0;
    }
    cnt1 += (sv[cnt1] <  k1) ? 1 : 0;
    cnt2 += (sv[cnt2] <= k2) ? 1 : 0;
    cnt3 += (sv[cnt3] <= p ) ? 1 : 0;

    const float T = sp[256];
    float contrib = (float)cnt1 * k1 - sp[cnt1]
                  + (T - sp[cnt2]) - (float)(256 - cnt2) * k2
                  - c1 * (float)(256 - cnt3);

#pragma unroll
    for (int off = 16; off > 0; off >>= 1)
        contrib += __shfl_xor_sync(0xffffffffu, contrib, off);
    if (lane == 0) red[wid] = contrib;
    __syncthreads();
    if (t == 0) {
        float tot = red[0] + red[1] + red[2] + red[3]
                  + red[4] + red[5] + red[6] + red[7];
        atomicAdd(&out[c], tot * inv);
    }
}

extern "C" void kernel_launch(void* const* d_in, const int* in_sizes, int n_in,
                              void* d_out, int out_size)
{
    (void)in_sizes; (void)n_in; (void)out_size;
    const float* pred = (const float*)d_in[0];
    const float* spac = (const float*)d_in[1];
    float* out = (float*)d_out;

    // Node 1: sort groups, publish, zero out. Triggers PDL completion early.
    sort_kernel<<<48, 256>>>(pred, out);

    // Node 2: queries, launched programmatically (prologue overlaps node 1).
    cudaLaunchConfig_t cfg = {};
    cfg.gridDim  = dim3(363, 1, 1);
    cfg.blockDim = dim3(256, 1, 1);
    cfg.dynamicSmemBytes = 0;
    cudaLaunchAttribute attrs[1];
    attrs[0].id = cudaLaunchAttributeProgrammaticStreamSerialization;
    attrs[0].val.programmaticStreamSerializationAllowed = 1;
    cfg.attrs = attrs;
    cfg.numAttrs = 1;
    cudaLaunchKernelEx(&cfg, query_kernel, pred, spac, out);
}

// round 16
// speedup vs baseline: 1.0090x; 1.0090x over previous
#include <cuda_runtime.h>

// DepthLoss3D: ONE main kernel with a grid-internal sort->query pipeline.
// Node 1 (PDL zeroer): out[0..2]=0, g_flag[0..47]=0, trigger.
// Node 2 (408 blocks):
//   bx<48  : sort (c,g) group (proven static bitonic) + scan, publish
//            g_sorted/g_prefix, gridsync, atomicAdd diag partial,
//            st.release g_flag = 1.
//   bx>=48 : pair (c,a>b). Full prologue (decode, p-load, constants) runs
//            concurrently with sorts; t0 spin-acquires the group's flag;
//            then proven closed form on the sorted arrays:
//            f(x)=max(x-ds,0.2ds-x,0)-0.2ds*[x<0];
//            sum = n1*k1 - P[n1] + (T-P[n2]) - (256-n2)*k2 - 0.2ds*(256-n3)
// All 408 blocks are co-resident in one wave -> spin is deadlock-free.

#define N_ELEM 4096

__device__ float g_sorted[3][16][256];
__device__ float g_prefix[3][16][257];
__device__ int   g_flag[48];

__device__ __forceinline__ int elem_index(int c, int g, int m) {
    if (c == 0)      return (g << 8) + m;
    else if (c == 1) return ((m >> 4) << 8) + (g << 4) + (m & 15);
    else             return (m << 4) + g;
}

__global__ void reset_kernel(float* __restrict__ out) {
    const int t = threadIdx.x;
    if (t < 48) g_flag[t] = 0;
    if (t < 3)  out[t] = 0.0f;
    cudaTriggerProgrammaticLaunchCompletion();
}

__global__ void __launch_bounds__(256) depthloss_pipe(
    const float* __restrict__ pred,   // [4096,3]
    const float* __restrict__ spac,   // [3]
    float* __restrict__ out)          // [3]
{
    __shared__ float sv[256];
    __shared__ float sp[257];
    __shared__ float red[8];

    const int t    = threadIdx.x;
    const int lane = t & 31;
    const int wid  = t >> 5;
    const int bx   = blockIdx.x;

    const float inv = 1.0f / ((float)N_ELEM * (float)N_ELEM);

    if (bx < 48) {
        // ================= SORT + DIAG BLOCK =================
        const int c = bx >> 4;
        const int g = bx & 15;

        float v = pred[elem_index(c, g, t) * 3 + c];

        // Static bitonic sort network (ascending by rank t), proven R6.
        const bool u2   = !(t & 2);
        const bool u4   = !(t & 4);
        const bool u8   = !(t & 8);
        const bool u16  = !(t & 16);
        const bool u32  = !(t & 32);
        const bool u64  = !(t & 64);
        const bool u128 = !(t & 128);

#define SH(J, UP) do {                                              \
            const float o_ = __shfl_xor_sync(0xffffffffu, v, (J));  \
            const bool mn_ = (((t & (J)) == 0) == (UP));            \
            v = mn_ ? fminf(v, o_) : fmaxf(v, o_);                  \
        } while (0)

#define SM(J, UP) do {                                              \
            sv[t] = v;                                              \
            __syncthreads();                                        \
            const float o_ = sv[t ^ (J)];                           \
            const bool mn_ = (((t & (J)) == 0) == (UP));            \
            v = mn_ ? fminf(v, o_) : fmaxf(v, o_);                  \
            __syncthreads();                                        \
        } while (0)

        SH(1, u2);
        SH(2, u4);  SH(1, u4);
        SH(4, u8);  SH(2, u8);  SH(1, u8);
        SH(8, u16); SH(4, u16); SH(2, u16); SH(1, u16);
        SH(16, u32); SH(8, u32); SH(4, u32); SH(2, u32); SH(1, u32);
        SM(32, u64); SH(16, u64); SH(8, u64); SH(4, u64); SH(2, u64); SH(1, u64);
        SM(64, u128); SM(32, u128); SH(16, u128); SH(8, u128); SH(4, u128);
        SH(2, u128); SH(1, u128);
        SM(128, true); SM(64, true); SM(32, true); SH(16, true); SH(8, true);
        SH(4, true); SH(2, true); SH(1, true);

#undef SH
#undef SM

        // Inclusive prefix scan of sorted v.
        float x = v;
#pragma unroll
        for (int off = 1; off < 32; off <<= 1) {
            const float y = __shfl_up_sync(0xffffffffu, x, off);
            if (lane >= off) x += y;
        }
        if (lane == 31) red[wid] = x;
        __syncthreads();
        float woff = 0.0f;
#pragma unroll
        for (int w = 0; w < 8; ++w)
            woff += (w < wid) ? red[w] : 0.0f;

        g_sorted[c][g][t]     = v;
        g_prefix[c][g][t + 1] = x + woff;
        if (t == 0) g_prefix[c][g][0] = 0.0f;

        // Diagonal partial: sum_r v_(r)*(2r-255).
        float w = v * (float)(2 * t - 255);
#pragma unroll
        for (int off = 16; off > 0; off >>= 1)
            w += __shfl_xor_sync(0xffffffffu, w, off);
        __syncthreads();
        if (lane == 0) red[wid] = w;
        __syncthreads();   // also orders all publish stores before the release

        if (t == 0) {
            const float tot = red[0] + red[1] + red[2] + red[3]
                            + red[4] + red[5] + red[6] + red[7];
            // Ensure node-1's reset of g_flag / out is done before we set it.
            cudaGridDependencySynchronize();
            atomicAdd(&out[c], tot * inv);
            asm volatile("st.release.gpu.global.b32 [%0], %1;"
                         :: "l"(&g_flag[bx]), "r"(1) : "memory");
        }
        return;
    }

    // ================= PAIR (QUERY) BLOCK =================
    const int idx = bx - 48;
    const int c   = idx / 120;
    const int pq  = idx - c * 120;
    int a = 1;
    while ((a + 1) * a / 2 <= pq) ++a;
    const int b = pq - a * (a - 1) / 2;

    // Prologue overlaps the sort blocks (no dependency yet).
    const float p  = pred[elem_index(c, a, t) * 3 + c];
    const float k  = spac[c] * 2.0f;
    const float ds = (float)a * k - (float)b * k;   // reference rounding order
    const float c1 = 0.2f * ds;
    const float k1 = p - ds;
    const float k2 = p - c1;

    // Wait for our group's sorted data.
    if (t == 0) {
        cudaGridDependencySynchronize();   // flag reset done before we read
        int ready;
        do {
            asm volatile("ld.relaxed.gpu.global.b32 %0, [%1];"
                         : "=r"(ready) : "l"(&g_flag[c * 16 + b]) : "memory");
            if (!ready) __nanosleep(64);
        } while (!ready);
        asm volatile("ld.acquire.gpu.global.b32 %0, [%1];"
                     : "=r"(ready) : "l"(&g_flag[c * 16 + b]) : "memory");
    }
    __syncthreads();

    sv[t] = g_sorted[c][b][t];
    sp[t] = g_prefix[c][b][t];
    if (t == 0) sp[256] = g_prefix[c][b][256];
    __syncthreads();

    // Closed form (proven).
    int cnt1 = 0, cnt2 = 0, cnt3 = 0;
#pragma unroll
    for (int s = 128; s > 0; s >>= 1) {
        cnt1 += (sv[cnt1 + s - 1] <  k1) ? s : 0;
        cnt2 += (sv[cnt2 + s - 1] <= k2) ? s : 0;
        cnt3 += (sv[cnt3 + s - 1] <= p ) ? s : 0;
    }
    cnt1 += (sv[cnt1] <  k1) ? 1 : 0;
    cnt2 += (sv[cnt2] <= k2) ? 1 : 0;
    cnt3 += (sv[cnt3] <= p ) ? 1 : 0;

    const float T = sp[256];
    float contrib = (float)cnt1 * k1 - sp[cnt1]
                  + (T - sp[cnt2]) - (float)(256 - cnt2) * k2
                  - c1 * (float)(256 - cnt3);

#pragma unroll
    for (int off = 16; off > 0; off >>= 1)
        contrib += __shfl_xor_sync(0xffffffffu, contrib, off);
    if (lane == 0) red[wid] = contrib;
    __syncthreads();
    if (t == 0) {
        const float tot = red[0] + red[1] + red[2] + red[3]
                        + red[4] + red[5] + red[6] + red[7];
        atomicAdd(&out[c], tot * inv);
    }
}

extern "C" void kernel_launch(void* const* d_in, const int* in_sizes, int n_in,
                              void* d_out, int out_size)
{
    (void)in_sizes; (void)n_in; (void)out_size;
    const float* pred = (const float*)d_in[0];
    const float* spac = (const float*)d_in[1];
    float* out = (float*)d_out;

    // Node 1: reset flags + zero out, trigger PDL completion.
    reset_kernel<<<1, 64>>>(out);

    // Node 2: pipelined main kernel (PDL).
    cudaLaunchConfig_t cfg = {};
    cfg.gridDim  = dim3(408, 1, 1);
    cfg.blockDim = dim3(256, 1, 1);
    cfg.dynamicSmemBytes = 0;
    cudaLaunchAttribute attrs[1];
    attrs[0].id = cudaLaunchAttributeProgrammaticStreamSerialization;
    attrs[0].val.programmaticStreamSerializationAllowed = 1;
    cfg.attrs = attrs;
    cfg.numAttrs = 1;
    cudaLaunchKernelEx(&cfg, depthloss_pipe, pred, spac, out);
}